// round 9
// baseline (speedup 1.0000x reference)
#include <cuda_runtime.h>
#include <cstdint>

#define HID 8192
#define BATCH 512
#define NIN 16
#define RANK 8
#define NOUT 4
#define GRID 256
#define TPB 256

// partials over 8 j-macros (1024 j each), folded in fixed order => deterministic
__device__ float g_u_part[8][BATCH * RANK];
__device__ float g_out_part[8][BATCH * NOUT];
__device__ unsigned int g_bar;   // monotone ticket counter, never reset (replay-safe)

typedef unsigned long long ull;

__device__ __forceinline__ void ffma2(ull& d, ull a, ull b) {
    asm("fma.rn.f32x2 %0, %1, %2, %0;" : "+l"(d) : "l"(a), "l"(b));
}
__device__ __forceinline__ void unpack2(float& lo, float& hi, ull v) {
    asm("mov.b64 {%0, %1}, %2;" : "=f"(lo), "=f"(hi) : "l"(v));
}
__device__ __forceinline__ uint32_t tf32_of(float x) {
    uint32_t u;
    asm("cvt.rna.tf32.f32 %0, %1;" : "=r"(u) : "f"(x));
    return u;
}
__device__ __forceinline__ void mma_16n8k8(float d[4],
                                           uint32_t a0, uint32_t a1, uint32_t a2, uint32_t a3,
                                           uint32_t b0, uint32_t b1) {
    asm volatile("mma.sync.aligned.m16n8k8.row.col.f32.tf32.tf32.f32 "
                 "{%0,%1,%2,%3}, {%4,%5,%6,%7}, {%8,%9}, {%0,%1,%2,%3};"
                 : "+f"(d[0]), "+f"(d[1]), "+f"(d[2]), "+f"(d[3])
                 : "r"(a0), "r"(a1), "r"(a2), "r"(a3), "r"(b0), "r"(b1));
}

__device__ __forceinline__ void grid_barrier() {
    __syncthreads();
    if (threadIdx.x == 0) {
        __threadfence();
        unsigned int old = atomicAdd(&g_bar, 1u);
        unsigned int target = (old / GRID + 1u) * GRID;
        while ((int)(*(volatile unsigned int*)&g_bar - target) < 0)
            __nanosleep(32);
        __threadfence();
    }
    __syncthreads();
}

__global__ void __launch_bounds__(TPB, 2) k_fused(const float* __restrict__ input,
                                                  const float* __restrict__ hidden,
                                                  const float* __restrict__ Win,
                                                  const float* __restrict__ L,
                                                  const float* __restrict__ R,
                                                  const float* __restrict__ Wout,
                                                  float* __restrict__ nh,
                                                  float* __restrict__ out) {
    const int t = threadIdx.x;
    const int lane = t & 31, w = t >> 5;
    const int g = lane >> 2;          // mma groupID
    const int q = lane & 3;           // mma threadID_in_group

    __shared__ float fold[8][16][8];                 // cross-warp mma fold
    __shared__ __align__(16) float comb[64][24];     // phase 2: [input(16) | u(8)]

    // ========== Phase 1 (MMA): u partials = tanh(h) @ R^T over 1024 j =====
    {
        const int bc = blockIdx.x >> 3;          // 0..31 -> 16 batch rows
        const int jm = blockIdx.x & 7;           // j-macro of 1024
        const int b0 = bc * 16;
        const int jbase = jm * 1024 + w * 128;

        const float* hr0 = hidden + (b0 + g) * HID;
        const float* hr8 = hidden + (b0 + g + 8) * HID;
        const float* Rr = R + g * HID;           // n = g

        float d[4] = {0.f, 0.f, 0.f, 0.f};
#pragma unroll
        for (int kk = 0; kk < 16; kk++) {
            const int j0 = jbase + kk * 8;
            float a0f = hr0[j0 + q];
            float a1f = hr8[j0 + q];
            float a2f = hr0[j0 + q + 4];
            float a3f = hr8[j0 + q + 4];
            float b0f = Rr[j0 + q];
            float b1f = Rr[j0 + q + 4];
            a0f = __tanhf(a0f); a1f = __tanhf(a1f);
            a2f = __tanhf(a2f); a3f = __tanhf(a3f);
            mma_16n8k8(d, tf32_of(a0f), tf32_of(a1f), tf32_of(a2f), tf32_of(a3f),
                       tf32_of(b0f), tf32_of(b1f));
        }

        // D: lane holds (g, 2q),(g,2q+1),(g+8,2q),(g+8,2q+1)
        fold[w][g][2 * q] = d[0];
        fold[w][g][2 * q + 1] = d[1];
        fold[w][g + 8][2 * q] = d[2];
        fold[w][g + 8][2 * q + 1] = d[3];
        __syncthreads();
        if (t < 128) {
            const int row = t >> 3, c = t & 7;
            float s = 0.0f;
#pragma unroll
            for (int w2 = 0; w2 < 8; w2++) s += fold[w2][row][c];
            g_u_part[jm][(b0 + row) * RANK + c] = s;
        }
    }

    grid_barrier();

    // ===================== Phase 2: new_h (exact fp32) ====================
    {
        const int jt = blockIdx.x & 31;          // 32 j-tiles of 256
        const int bc = blockIdx.x >> 5;          // 8 batch chunks of 64
        const int b0 = bc * 64;
        const int jg = t & 127;                  // 128 groups of 2 j
        const int bs = t >> 7;                   // 0..1
        const int j0 = jt * 256 + jg * 2;

        // stage [input | u] per batch row: comb[bi][0..15]=input, [16..23]=u
        for (int v = t; v < 64 * 24; v += TPB) {
            const int bi = v / 24, c = v - bi * 24;
            float val;
            if (c < NIN) {
                val = input[(b0 + bi) * NIN + c];
            } else {
                const int idx = (b0 + bi) * RANK + (c - NIN);
                float s = 0.0f;
#pragma unroll
                for (int p = 0; p < 8; p++) s += g_u_part[p][idx];
                val = s * (1.0f / (float)HID);
            }
            comb[bi][c] = val;
        }

        ull wj[2][8];
        ull lj[2][4];
#pragma unroll
        for (int jj = 0; jj < 2; jj++) {
            const ull* wr = (const ull*)(Win + (j0 + jj) * NIN);
#pragma unroll
            for (int i = 0; i < 8; i++) wj[jj][i] = wr[i];
            const ull* lr = (const ull*)(L + (j0 + jj) * RANK);
#pragma unroll
            for (int r = 0; r < 4; r++) lj[jj][r] = lr[r];
        }
        __syncthreads();

#pragma unroll 4
        for (int bi = bs; bi < 64; bi += 2) {
            const int b = b0 + bi;

            union { float4 f4[6]; ull p[12]; } cb;
            const float4* cp = (const float4*)&comb[bi][0];
#pragma unroll
            for (int qq = 0; qq < 6; qq++) cb.f4[qq] = cp[qq];

            float2 h2 = *(const float2*)(hidden + b * HID + j0);

            float res[2];
#pragma unroll
            for (int jj = 0; jj < 2; jj++) {
                ull acc = 0ULL;
#pragma unroll
                for (int i = 0; i < 8; i++) ffma2(acc, wj[jj][i], cb.p[i]);
#pragma unroll
                for (int r = 0; r < 4; r++) ffma2(acc, lj[jj][r], cb.p[8 + r]);
                float lo, hi;
                unpack2(lo, hi, acc);
                res[jj] = lo + hi;
            }

            float2 o;
            o.x = fmaf(0.1f, res[0], 0.9f * h2.x);
            o.y = fmaf(0.1f, res[1], 0.9f * h2.y);
            *(float2*)(nh + b * HID + j0) = o;
        }
    }

    grid_barrier();

    // ========== Phase 3 (MMA): out partials = tanh(nh) @ Wout^T ===========
    {
        const int bc = blockIdx.x >> 3;
        const int jm = blockIdx.x & 7;
        const int b0 = bc * 16;
        const int jbase = jm * 1024 + w * 128;

        const float* xr0 = nh + (b0 + g) * HID;
        const float* xr8 = nh + (b0 + g + 8) * HID;
        const bool have_w = (g < NOUT);
        const float* Wr = Wout + (have_w ? g : 0) * HID;

        float d[4] = {0.f, 0.f, 0.f, 0.f};
#pragma unroll
        for (int kk = 0; kk < 16; kk++) {
            const int j0 = jbase + kk * 8;
            float a0f = xr0[j0 + q];
            float a1f = xr8[j0 + q];
            float a2f = xr0[j0 + q + 4];
            float a3f = xr8[j0 + q + 4];
            float b0f = have_w ? Wr[j0 + q] : 0.0f;
            float b1f = have_w ? Wr[j0 + q + 4] : 0.0f;
            a0f = __tanhf(a0f); a1f = __tanhf(a1f);
            a2f = __tanhf(a2f); a3f = __tanhf(a3f);
            mma_16n8k8(d, tf32_of(a0f), tf32_of(a1f), tf32_of(a2f), tf32_of(a3f),
                       tf32_of(b0f), tf32_of(b1f));
        }

        __syncthreads();   // fold[] reuse
        fold[w][g][2 * q] = d[0];
        fold[w][g][2 * q + 1] = d[1];
        fold[w][g + 8][2 * q] = d[2];
        fold[w][g + 8][2 * q + 1] = d[3];
        __syncthreads();
        if (t < 128) {
            const int row = t >> 3, c = t & 7;
            if (c < NOUT) {
                float s = 0.0f;
#pragma unroll
                for (int w2 = 0; w2 < 8; w2++) s += fold[w2][row][c];
                g_out_part[jm][(b0 + row) * NOUT + c] = s;
            }
        }
    }

    grid_barrier();

    // ===================== Phase 4: tiny final fold =======================
    {
        const int idx = blockIdx.x * TPB + t;
        if (idx < BATCH * NOUT) {
            float s = 0.0f;
#pragma unroll
            for (int jm = 0; jm < 8; jm++) s += g_out_part[jm][idx];
            out[idx] = s * (1.0f / (float)HID);
        }
    }
}

extern "C" void kernel_launch(void* const* d_in, const int* in_sizes, int n_in,
                              void* d_out, int out_size) {
    const float* input  = (const float*)d_in[0];  // [512,16]
    const float* hidden = (const float*)d_in[1];  // [512,8192]
    const float* Win    = (const float*)d_in[2];  // [8192,16]
    const float* L      = (const float*)d_in[3];  // [8192,8]
    const float* R      = (const float*)d_in[4];  // [8,8192]
    const float* Wout   = (const float*)d_in[5];  // [4,8192]

    float* out = (float*)d_out;                   // [512,4] then [512,8192]
    float* nh  = out + BATCH * NOUT;

    k_fused<<<GRID, TPB>>>(input, hidden, Win, L, R, Wout, nh, out);
}